// round 9
// baseline (speedup 1.0000x reference)
#include <cuda_runtime.h>

// BSplineEncoder: out[n, c] = b[c] + sum_k basis_k(x[n]) * W[c, k]
// Cubic clamped-uniform B-spline, 10 basis fns, 7 spans on [0,1].
//
// R8 post-mortem: persistent kernel regressed (per-tile barrier bubbles).
// R9 = champion R4 macro-structure, with the dot product re-associated so
// FFMA2 operands come straight from LDS results: acc_c += {B2i,B2i+1} *
// {Wc,2i,Wc,2i+1}, horizontal add at the end. Removes 10 dup movs/iter.

#define N_BASIS 10
#define BAS_PAD 12            // 10 floats padded to 12 (48 B, 16B-aligned rows)
#define CH      128
#define TILE    256
#define NTHREADS 256

using u64 = unsigned long long;

__device__ __forceinline__ u64 pack2(float lo, float hi) {
    u64 d; asm("mov.b64 %0, {%1, %2};" : "=l"(d) : "f"(lo), "f"(hi)); return d;
}
__device__ __forceinline__ void unpack2(u64 v, float& lo, float& hi) {
    asm("mov.b64 {%0, %1}, %2;" : "=f"(lo), "=f"(hi) : "l"(v));
}
// packed fp32x2 FMA: d = a*b + c on both halves (Blackwell 2x fp32 path)
__device__ __forceinline__ u64 ffma2(u64 a, u64 b, u64 c) {
    u64 d; asm("fma.rn.f32x2 %0, %1, %2, %3;" : "=l"(d) : "l"(a), "l"(b), "l"(c)); return d;
}

__global__ __launch_bounds__(NTHREADS)
void bspline_encoder_kernel(const float* __restrict__ x,
                            const float* __restrict__ W,    // [128, 10] row-major
                            const float* __restrict__ bias, // [128]
                            float* __restrict__ out,        // [n, 128]
                            int n)
{
    __shared__ float sB[TILE][BAS_PAD];   // non-duplicated basis, 48 B rows
    __shared__ float sWf[CH * N_BASIS];   // staged W for register fill
    __shared__ float sBias[CH];

    const int tid  = threadIdx.x;
    const int warp = tid >> 5;
    const int lane = tid & 31;
    const int base = blockIdx.x * TILE;

    // ---- Stage W + bias into smem (coalesced, one-time) ----
    for (int idx = tid; idx < CH * N_BASIS; idx += NTHREADS) sWf[idx] = W[idx];
    if (tid < CH) sBias[tid] = bias[tid];

    // ---- Phase 1: one thread per x, Cox-de Boor (degree 3), scatter into dense 10-vec ----
    {
        int t = base + tid;
        #pragma unroll
        for (int k = 0; k < BAS_PAD; k++) sB[tid][k] = 0.0f;

        if (t < n) {
            float xv = x[t];
            xv = fminf(fmaxf(xv, 1e-9f), 1.0f);
            const float inv7 = 1.0f / 7.0f;
            int j = (int)(xv * 7.0f);
            j = min(j, 6);

            float left1  = xv - (float)j * inv7;
            float left2  = xv - (float)max(j - 1, 0) * inv7;
            float left3  = xv - (float)max(j - 2, 0) * inv7;
            float right1 = (float)min(j + 1, 7) * inv7 - xv;
            float right2 = (float)min(j + 2, 7) * inv7 - xv;
            float right3 = (float)min(j + 3, 7) * inv7 - xv;

            float N0 = 1.0f, N1, N2, N3, saved, temp;
            // d = 1
            temp = N0 / (right1 + left1);
            N0 = right1 * temp;
            N1 = left1 * temp;
            // d = 2
            temp = N0 / (right1 + left2);
            N0 = right1 * temp;  saved = left2 * temp;
            temp = N1 / (right2 + left1);
            N1 = saved + right2 * temp;
            N2 = left1 * temp;
            // d = 3
            temp = N0 / (right1 + left3);
            N0 = right1 * temp;  saved = left3 * temp;
            temp = N1 / (right2 + left2);
            N1 = saved + right2 * temp;  saved = left2 * temp;
            temp = N2 / (right3 + left1);
            N2 = saved + right3 * temp;
            N3 = left1 * temp;

            // Reference uses strict x < knot indicators: basis == 0 at x == 1.0
            if (xv < 1.0f) {
                sB[tid][j + 0] = N0;
                sB[tid][j + 1] = N1;
                sB[tid][j + 2] = N2;
                sB[tid][j + 3] = N3;
            }
        }
    }
    __syncthreads();

    // ---- Fill per-lane W registers: 4 channels (c = 4*lane + 0..3) as k-pairs ----
    // wc[c][i] = {W[c][2i], W[c][2i+1]}  (5 pairs per channel)
    u64 wc0[5], wc1[5], wc2[5], wc3[5];
    {
        const float* w0 = sWf + (lane * 4 + 0) * N_BASIS;
        const float* w1 = sWf + (lane * 4 + 1) * N_BASIS;
        const float* w2 = sWf + (lane * 4 + 2) * N_BASIS;
        const float* w3 = sWf + (lane * 4 + 3) * N_BASIS;
        #pragma unroll
        for (int i = 0; i < 5; i++) {
            wc0[i] = pack2(w0[2 * i], w0[2 * i + 1]);
            wc1[i] = pack2(w1[2 * i], w1[2 * i + 1]);
            wc2[i] = pack2(w2[2 * i], w2[2 * i + 1]);
            wc3[i] = pack2(w3[2 * i], w3[2 * i + 1]);
        }
    }
    // Accumulator seeds: {bias_c, 0}
    const u64 s0 = pack2(sBias[lane * 4 + 0], 0.0f);
    const u64 s1 = pack2(sBias[lane * 4 + 1], 0.0f);
    const u64 s2 = pack2(sBias[lane * 4 + 2], 0.0f);
    const u64 s3 = pack2(sBias[lane * 4 + 3], 0.0f);

    // ---- Phase 2: warp-per-x, 3 broadcast LDS.128 + 20 FFMA2 + 4 FADD + STG.128 ----
    const int lim = min(TILE, n - base);
    float* outLane = out + (size_t)base * CH + lane * 4;

    #pragma unroll 4
    for (int t = warp; t < lim; t += 8) {
        // Basis pairs straight from smem: p[i] = {B2i, B2i+1}
        const ulonglong2* r = reinterpret_cast<const ulonglong2*>(&sB[t][0]);
        ulonglong2 r0 = r[0];   // {B0,B1},{B2,B3}
        ulonglong2 r1 = r[1];   // {B4,B5},{B6,B7}
        ulonglong2 r2 = r[2];   // {B8,B9},{pad,pad}

        u64 a0 = s0, a1 = s1, a2 = s2, a3 = s3;
        a0 = ffma2(r0.x, wc0[0], a0);
        a1 = ffma2(r0.x, wc1[0], a1);
        a2 = ffma2(r0.x, wc2[0], a2);
        a3 = ffma2(r0.x, wc3[0], a3);
        a0 = ffma2(r0.y, wc0[1], a0);
        a1 = ffma2(r0.y, wc1[1], a1);
        a2 = ffma2(r0.y, wc2[1], a2);
        a3 = ffma2(r0.y, wc3[1], a3);
        a0 = ffma2(r1.x, wc0[2], a0);
        a1 = ffma2(r1.x, wc1[2], a1);
        a2 = ffma2(r1.x, wc2[2], a2);
        a3 = ffma2(r1.x, wc3[2], a3);
        a0 = ffma2(r1.y, wc0[3], a0);
        a1 = ffma2(r1.y, wc1[3], a1);
        a2 = ffma2(r1.y, wc2[3], a2);
        a3 = ffma2(r1.y, wc3[3], a3);
        a0 = ffma2(r2.x, wc0[4], a0);
        a1 = ffma2(r2.x, wc1[4], a1);
        a2 = ffma2(r2.x, wc2[4], a2);
        a3 = ffma2(r2.x, wc3[4], a3);

        // Horizontal add: out[c] = lo(acc_c) + hi(acc_c)  (bias already seeded)
        float l0, h0, l1, h1, l2, h2, l3, h3;
        unpack2(a0, l0, h0);
        unpack2(a1, l1, h1);
        unpack2(a2, l2, h2);
        unpack2(a3, l3, h3);
        float4 o;
        o.x = l0 + h0;
        o.y = l1 + h1;
        o.z = l2 + h2;
        o.w = l3 + h3;

        // streaming store: output far exceeds L2, no reuse
        __stcs(reinterpret_cast<float4*>(outLane + (size_t)t * CH), o);
    }
}

extern "C" void kernel_launch(void* const* d_in, const int* in_sizes, int n_in,
                              void* d_out, int out_size) {
    const float* x    = (const float*)d_in[0];
    const float* W    = (const float*)d_in[1];
    const float* bias = (const float*)d_in[2];
    float* out = (float*)d_out;

    int n = in_sizes[0];                    // 512 * 2048 = 1,048,576
    int blocks = (n + TILE - 1) / TILE;     // 4096
    bspline_encoder_kernel<<<blocks, NTHREADS>>>(x, W, bias, out, n);
}

// round 10
// speedup vs baseline: 1.6866x; 1.6866x over previous
#include <cuda_runtime.h>

// BSplineEncoder: out[n, c] = b[c] + sum_k basis_k(x[n]) * W[c, k]
// Cubic clamped-uniform B-spline, 10 basis fns, 7 spans on [0,1].
//
// R9 post-mortem: feeding fma.f32x2 from LDS-reinterpreted u64s broke the
// packed path (scalar fallback, 1.7x slower). Champion remains the R4 body:
// dup-mov packs keep FFMA2 operands register-born. R10 = exact R4 body with
// one isolated change: phase-2 unroll 4 -> 8 (deeper LDS/STG batching),
// fenced by __launch_bounds__(256,3) so occupancy cannot regress.

#define N_BASIS 10
#define BAS_PAD 12            // 10 floats padded to 12 (48 B, 16B-aligned rows)
#define CH      128
#define TILE    256
#define NTHREADS 256

using u64 = unsigned long long;

__device__ __forceinline__ u64 pack2(float lo, float hi) {
    u64 d; asm("mov.b64 %0, {%1, %2};" : "=l"(d) : "f"(lo), "f"(hi)); return d;
}
__device__ __forceinline__ void unpack2(u64 v, float& lo, float& hi) {
    asm("mov.b64 {%0, %1}, %2;" : "=f"(lo), "=f"(hi) : "l"(v));
}
// packed fp32x2 FMA: d = a*b + c on both halves (Blackwell 2x fp32 path)
__device__ __forceinline__ u64 ffma2(u64 a, u64 b, u64 c) {
    u64 d; asm("fma.rn.f32x2 %0, %1, %2, %3;" : "=l"(d) : "l"(a), "l"(b), "l"(c)); return d;
}

__global__ __launch_bounds__(NTHREADS, 3)
void bspline_encoder_kernel(const float* __restrict__ x,
                            const float* __restrict__ W,    // [128, 10] row-major
                            const float* __restrict__ bias, // [128]
                            float* __restrict__ out,        // [n, 128]
                            int n)
{
    __shared__ float sB[TILE][BAS_PAD];   // non-duplicated basis, 48 B rows
    __shared__ float sWf[CH * N_BASIS];   // staged W for register fill
    __shared__ float sBias[CH];

    const int tid  = threadIdx.x;
    const int warp = tid >> 5;
    const int lane = tid & 31;
    const int base = blockIdx.x * TILE;

    // ---- Stage W + bias into smem (coalesced, one-time) ----
    for (int idx = tid; idx < CH * N_BASIS; idx += NTHREADS) sWf[idx] = W[idx];
    if (tid < CH) sBias[tid] = bias[tid];

    // ---- Phase 1: one thread per x, Cox-de Boor (degree 3), scatter into dense 10-vec ----
    {
        int t = base + tid;
        #pragma unroll
        for (int k = 0; k < BAS_PAD; k++) sB[tid][k] = 0.0f;

        if (t < n) {
            float xv = x[t];
            xv = fminf(fmaxf(xv, 1e-9f), 1.0f);
            const float inv7 = 1.0f / 7.0f;
            int j = (int)(xv * 7.0f);
            j = min(j, 6);

            float left1  = xv - (float)j * inv7;
            float left2  = xv - (float)max(j - 1, 0) * inv7;
            float left3  = xv - (float)max(j - 2, 0) * inv7;
            float right1 = (float)min(j + 1, 7) * inv7 - xv;
            float right2 = (float)min(j + 2, 7) * inv7 - xv;
            float right3 = (float)min(j + 3, 7) * inv7 - xv;

            float N0 = 1.0f, N1, N2, N3, saved, temp;
            // d = 1
            temp = N0 / (right1 + left1);
            N0 = right1 * temp;
            N1 = left1 * temp;
            // d = 2
            temp = N0 / (right1 + left2);
            N0 = right1 * temp;  saved = left2 * temp;
            temp = N1 / (right2 + left1);
            N1 = saved + right2 * temp;
            N2 = left1 * temp;
            // d = 3
            temp = N0 / (right1 + left3);
            N0 = right1 * temp;  saved = left3 * temp;
            temp = N1 / (right2 + left2);
            N1 = saved + right2 * temp;  saved = left2 * temp;
            temp = N2 / (right3 + left1);
            N2 = saved + right3 * temp;
            N3 = left1 * temp;

            // Reference uses strict x < knot indicators: basis == 0 at x == 1.0
            if (xv < 1.0f) {
                sB[tid][j + 0] = N0;
                sB[tid][j + 1] = N1;
                sB[tid][j + 2] = N2;
                sB[tid][j + 3] = N3;
            }
        }
    }
    __syncthreads();

    // ---- Fill per-lane W registers: 4 channels (c = 4*lane + 0..3), pairs packed f32x2 ----
    u64 wlo[N_BASIS], whi[N_BASIS];
    {
        const float* w0 = sWf + (lane * 4 + 0) * N_BASIS;
        const float* w1 = sWf + (lane * 4 + 1) * N_BASIS;
        const float* w2 = sWf + (lane * 4 + 2) * N_BASIS;
        const float* w3 = sWf + (lane * 4 + 3) * N_BASIS;
        #pragma unroll
        for (int k = 0; k < N_BASIS; k++) {
            wlo[k] = pack2(w0[k], w1[k]);
            whi[k] = pack2(w2[k], w3[k]);
        }
    }
    const u64 blo = pack2(sBias[lane * 4 + 0], sBias[lane * 4 + 1]);
    const u64 bhi = pack2(sBias[lane * 4 + 2], sBias[lane * 4 + 3]);

    // ---- Phase 2: warp-per-x, 3 broadcast LDS.128 + 10 dup movs + 20 FFMA2 + 1 STG.128 ----
    const int lim = min(TILE, n - base);
    float* outLane = out + (size_t)base * CH + lane * 4;

    #pragma unroll 8
    for (int t = warp; t < lim; t += 8) {
        const float4* r = reinterpret_cast<const float4*>(&sB[t][0]);
        float4 b0 = r[0];   // B0..B3
        float4 b1 = r[1];   // B4..B7
        float4 b2 = r[2];   // B8, B9, pad, pad

        u64 acc_lo = blo, acc_hi = bhi;
        u64 a;
        a = pack2(b0.x, b0.x); acc_lo = ffma2(a, wlo[0], acc_lo); acc_hi = ffma2(a, whi[0], acc_hi);
        a = pack2(b0.y, b0.y); acc_lo = ffma2(a, wlo[1], acc_lo); acc_hi = ffma2(a, whi[1], acc_hi);
        a = pack2(b0.z, b0.z); acc_lo = ffma2(a, wlo[2], acc_lo); acc_hi = ffma2(a, whi[2], acc_hi);
        a = pack2(b0.w, b0.w); acc_lo = ffma2(a, wlo[3], acc_lo); acc_hi = ffma2(a, whi[3], acc_hi);
        a = pack2(b1.x, b1.x); acc_lo = ffma2(a, wlo[4], acc_lo); acc_hi = ffma2(a, whi[4], acc_hi);
        a = pack2(b1.y, b1.y); acc_lo = ffma2(a, wlo[5], acc_lo); acc_hi = ffma2(a, whi[5], acc_hi);
        a = pack2(b1.z, b1.z); acc_lo = ffma2(a, wlo[6], acc_lo); acc_hi = ffma2(a, whi[6], acc_hi);
        a = pack2(b1.w, b1.w); acc_lo = ffma2(a, wlo[7], acc_lo); acc_hi = ffma2(a, whi[7], acc_hi);
        a = pack2(b2.x, b2.x); acc_lo = ffma2(a, wlo[8], acc_lo); acc_hi = ffma2(a, whi[8], acc_hi);
        a = pack2(b2.y, b2.y); acc_lo = ffma2(a, wlo[9], acc_lo); acc_hi = ffma2(a, whi[9], acc_hi);

        float4 o;
        unpack2(acc_lo, o.x, o.y);
        unpack2(acc_hi, o.z, o.w);
        // streaming store: output far exceeds L2, no reuse
        __stcs(reinterpret_cast<float4*>(outLane + (size_t)t * CH), o);
    }
}

extern "C" void kernel_launch(void* const* d_in, const int* in_sizes, int n_in,
                              void* d_out, int out_size) {
    const float* x    = (const float*)d_in[0];
    const float* W    = (const float*)d_in[1];
    const float* bias = (const float*)d_in[2];
    float* out = (float*)d_out;

    int n = in_sizes[0];                    // 512 * 2048 = 1,048,576
    int blocks = (n + TILE - 1) / TILE;     // 4096
    bspline_encoder_kernel<<<blocks, NTHREADS>>>(x, W, bias, out, n);
}

// round 11
// speedup vs baseline: 1.6901x; 1.0021x over previous
#include <cuda_runtime.h>

// BSplineEncoder: out[n, c] = b[c] + sum_k basis_k(x[n]) * W[c, k]
// Cubic clamped-uniform B-spline, 10 basis fns, 7 spans on [0,1].
//
// CHAMPION (R4 body, 76.6 us, DRAM 74.6%). Series evidence: ILP (R5),
// occupancy (R6), persistence (R8), re-association (R9), unroll-8 (R10)
// all regressed or were neutral; DRAM is pinned at ~74.5% across every
// good variant -> practical HBM3e write-stream ceiling. This is the
// best-known configuration: warp-per-x, per-lane W in registers as f32x2
// pairs, 3 broadcast LDS.128 + 10 dup movs + 20 FFMA2 + 1 STG.128(.cs).

#define N_BASIS 10
#define BAS_PAD 12            // 10 floats padded to 12 (48 B, 16B-aligned rows)
#define CH      128
#define TILE    256
#define NTHREADS 256

using u64 = unsigned long long;

__device__ __forceinline__ u64 pack2(float lo, float hi) {
    u64 d; asm("mov.b64 %0, {%1, %2};" : "=l"(d) : "f"(lo), "f"(hi)); return d;
}
__device__ __forceinline__ void unpack2(u64 v, float& lo, float& hi) {
    asm("mov.b64 {%0, %1}, %2;" : "=f"(lo), "=f"(hi) : "l"(v));
}
// packed fp32x2 FMA: d = a*b + c on both halves (Blackwell 2x fp32 path)
__device__ __forceinline__ u64 ffma2(u64 a, u64 b, u64 c) {
    u64 d; asm("fma.rn.f32x2 %0, %1, %2, %3;" : "=l"(d) : "l"(a), "l"(b), "l"(c)); return d;
}

__global__ __launch_bounds__(NTHREADS)
void bspline_encoder_kernel(const float* __restrict__ x,
                            const float* __restrict__ W,    // [128, 10] row-major
                            const float* __restrict__ bias, // [128]
                            float* __restrict__ out,        // [n, 128]
                            int n)
{
    __shared__ float sB[TILE][BAS_PAD];   // non-duplicated basis, 48 B rows
    __shared__ float sWf[CH * N_BASIS];   // staged W for register fill
    __shared__ float sBias[CH];

    const int tid  = threadIdx.x;
    const int warp = tid >> 5;
    const int lane = tid & 31;
    const int base = blockIdx.x * TILE;

    // ---- Stage W + bias into smem (coalesced, one-time) ----
    for (int idx = tid; idx < CH * N_BASIS; idx += NTHREADS) sWf[idx] = W[idx];
    if (tid < CH) sBias[tid] = bias[tid];

    // ---- Phase 1: one thread per x, Cox-de Boor (degree 3), scatter into dense 10-vec ----
    {
        int t = base + tid;
        #pragma unroll
        for (int k = 0; k < BAS_PAD; k++) sB[tid][k] = 0.0f;

        if (t < n) {
            float xv = x[t];
            xv = fminf(fmaxf(xv, 1e-9f), 1.0f);
            const float inv7 = 1.0f / 7.0f;
            int j = (int)(xv * 7.0f);
            j = min(j, 6);

            float left1  = xv - (float)j * inv7;
            float left2  = xv - (float)max(j - 1, 0) * inv7;
            float left3  = xv - (float)max(j - 2, 0) * inv7;
            float right1 = (float)min(j + 1, 7) * inv7 - xv;
            float right2 = (float)min(j + 2, 7) * inv7 - xv;
            float right3 = (float)min(j + 3, 7) * inv7 - xv;

            float N0 = 1.0f, N1, N2, N3, saved, temp;
            // d = 1
            temp = N0 / (right1 + left1);
            N0 = right1 * temp;
            N1 = left1 * temp;
            // d = 2
            temp = N0 / (right1 + left2);
            N0 = right1 * temp;  saved = left2 * temp;
            temp = N1 / (right2 + left1);
            N1 = saved + right2 * temp;
            N2 = left1 * temp;
            // d = 3
            temp = N0 / (right1 + left3);
            N0 = right1 * temp;  saved = left3 * temp;
            temp = N1 / (right2 + left2);
            N1 = saved + right2 * temp;  saved = left2 * temp;
            temp = N2 / (right3 + left1);
            N2 = saved + right3 * temp;
            N3 = left1 * temp;

            // Reference uses strict x < knot indicators: basis == 0 at x == 1.0
            if (xv < 1.0f) {
                sB[tid][j + 0] = N0;
                sB[tid][j + 1] = N1;
                sB[tid][j + 2] = N2;
                sB[tid][j + 3] = N3;
            }
        }
    }
    __syncthreads();

    // ---- Fill per-lane W registers: 4 channels (c = 4*lane + 0..3), pairs packed f32x2 ----
    u64 wlo[N_BASIS], whi[N_BASIS];
    {
        const float* w0 = sWf + (lane * 4 + 0) * N_BASIS;
        const float* w1 = sWf + (lane * 4 + 1) * N_BASIS;
        const float* w2 = sWf + (lane * 4 + 2) * N_BASIS;
        const float* w3 = sWf + (lane * 4 + 3) * N_BASIS;
        #pragma unroll
        for (int k = 0; k < N_BASIS; k++) {
            wlo[k] = pack2(w0[k], w1[k]);
            whi[k] = pack2(w2[k], w3[k]);
        }
    }
    const u64 blo = pack2(sBias[lane * 4 + 0], sBias[lane * 4 + 1]);
    const u64 bhi = pack2(sBias[lane * 4 + 2], sBias[lane * 4 + 3]);

    // ---- Phase 2: warp-per-x, 3 broadcast LDS.128 + 10 dup movs + 20 FFMA2 + 1 STG.128 ----
    const int lim = min(TILE, n - base);
    float* outLane = out + (size_t)base * CH + lane * 4;

    #pragma unroll 4
    for (int t = warp; t < lim; t += 8) {
        const float4* r = reinterpret_cast<const float4*>(&sB[t][0]);
        float4 b0 = r[0];   // B0..B3
        float4 b1 = r[1];   // B4..B7
        float4 b2 = r[2];   // B8, B9, pad, pad

        u64 acc_lo = blo, acc_hi = bhi;
        u64 a;
        a = pack2(b0.x, b0.x); acc_lo = ffma2(a, wlo[0], acc_lo); acc_hi = ffma2(a, whi[0], acc_hi);
        a = pack2(b0.y, b0.y); acc_lo = ffma2(a, wlo[1], acc_lo); acc_hi = ffma2(a, whi[1], acc_hi);
        a = pack2(b0.z, b0.z); acc_lo = ffma2(a, wlo[2], acc_lo); acc_hi = ffma2(a, whi[2], acc_hi);
        a = pack2(b0.w, b0.w); acc_lo = ffma2(a, wlo[3], acc_lo); acc_hi = ffma2(a, whi[3], acc_hi);
        a = pack2(b1.x, b1.x); acc_lo = ffma2(a, wlo[4], acc_lo); acc_hi = ffma2(a, whi[4], acc_hi);
        a = pack2(b1.y, b1.y); acc_lo = ffma2(a, wlo[5], acc_lo); acc_hi = ffma2(a, whi[5], acc_hi);
        a = pack2(b1.z, b1.z); acc_lo = ffma2(a, wlo[6], acc_lo); acc_hi = ffma2(a, whi[6], acc_hi);
        a = pack2(b1.w, b1.w); acc_lo = ffma2(a, wlo[7], acc_lo); acc_hi = ffma2(a, whi[7], acc_hi);
        a = pack2(b2.x, b2.x); acc_lo = ffma2(a, wlo[8], acc_lo); acc_hi = ffma2(a, whi[8], acc_hi);
        a = pack2(b2.y, b2.y); acc_lo = ffma2(a, wlo[9], acc_lo); acc_hi = ffma2(a, whi[9], acc_hi);

        float4 o;
        unpack2(acc_lo, o.x, o.y);
        unpack2(acc_hi, o.z, o.w);
        // streaming store: output far exceeds L2, no reuse
        __stcs(reinterpret_cast<float4*>(outLane + (size_t)t * CH), o);
    }
}

extern "C" void kernel_launch(void* const* d_in, const int* in_sizes, int n_in,
                              void* d_out, int out_size) {
    const float* x    = (const float*)d_in[0];
    const float* W    = (const float*)d_in[1];
    const float* bias = (const float*)d_in[2];
    float* out = (float*)d_out;

    int n = in_sizes[0];                    // 512 * 2048 = 1,048,576
    int blocks = (n + TILE - 1) / TILE;     // 4096
    bspline_encoder_kernel<<<blocks, NTHREADS>>>(x, W, bias, out, n);
}